// round 8
// baseline (speedup 1.0000x reference)
#include <cuda_runtime.h>
#include <stdint.h>
#include <math.h>

#define BB  4
#define TT  256
#define TS  512
#define HH  1024
#define VV  32100
#define NROW (BB*TT)
#define N4  (VV/4)          // 8025 float4 per row
#define ROWBYTES (VV*4)     // 128400 B

#define HSLOTS 2048
#define HMASK  (HSLOTS-1)
#define PGRID  148

// 4 segments of the row buffer: segs 0-2 = 2048 float4 (32768 B), seg 3 = 1881 float4 (30096 B)
#define SEGF4   2048
#define SEGB    32768
#define SEG3B   (ROWBYTES - 3*SEGB)   // 30096

#define OFF_ROW   0
#define OFF_HKEY  128512
#define OFF_HVAL  (OFF_HKEY + HSLOTS*4)
#define OFF_RED   (OFF_HVAL + HSLOTS*4)
#define OFF_MBAR  (OFF_RED + 96*4)
#define SMEM_TOT  (OFF_MBAR + 4*8 + 16)

__device__ float g_encproj[BB * TS];
__device__ float g_decproj[BB * TT];

__device__ __forceinline__ uint32_t smem_u32(const void* p) {
    uint32_t a;
    asm("{ .reg .u64 t; cvta.to.shared.u64 t, %1; cvt.u32.u64 %0, t; }"
        : "=r"(a) : "l"(p));
    return a;
}
__device__ __forceinline__ void mbar_init(uint32_t mbar, uint32_t cnt) {
    asm volatile("mbarrier.init.shared.b64 [%0], %1;" :: "r"(mbar), "r"(cnt) : "memory");
}
__device__ __forceinline__ void mbar_expect_tx(uint32_t mbar, uint32_t bytes) {
    asm volatile("mbarrier.arrive.expect_tx.shared.b64 _, [%0], %1;"
                 :: "r"(mbar), "r"(bytes) : "memory");
}
__device__ __forceinline__ void mbar_wait(uint32_t mbar, uint32_t phase) {
    asm volatile(
        "{\n\t.reg .pred P;\n\t"
        "W_%=:\n\t"
        "mbarrier.try_wait.parity.acquire.cta.shared::cta.b64 P, [%0], %1, 0x989680;\n\t"
        "@P bra D_%=;\n\t"
        "bra W_%=;\n\t"
        "D_%=:\n\t}"
        :: "r"(mbar), "r"(phase) : "memory");
}
__device__ __forceinline__ void tma_1d_g2s(uint32_t dst, const void* src,
                                           uint32_t bytes, uint32_t mbar) {
    asm volatile(
        "cp.async.bulk.shared::cta.global.mbarrier::complete_tx::bytes [%0], [%1], %2, [%3];"
        :: "r"(dst), "l"(src), "r"(bytes), "r"(mbar) : "memory");
}

// ---------------------------------------------------------------------------
// Kernel 1: one warp per row dot(row, W); replaces the einsum via
//   context . W_top == sum_s attn[s] * (enc[s] . W_top)
// ---------------------------------------------------------------------------
__global__ void proj_kernel(const float* __restrict__ dec,
                            const float* __restrict__ enc,
                            const float* __restrict__ Wg,
                            const float* __restrict__ bg)
{
    const int gw   = (blockIdx.x * blockDim.x + threadIdx.x) >> 5;
    const int lane = threadIdx.x & 31;
    const int nEnc = BB * TS;
    const int nDec = BB * TT;

    if (gw < nEnc) {
        const float4* row = (const float4*)(enc + (size_t)gw * HH);
        const float4* w   = (const float4*)(Wg);
        float s = 0.f;
        #pragma unroll
        for (int i = 0; i < HH / 128; ++i) {
            float4 a = row[lane + i * 32];
            float4 b = w[lane + i * 32];
            s += a.x * b.x + a.y * b.y + a.z * b.z + a.w * b.w;
        }
        #pragma unroll
        for (int o = 16; o > 0; o >>= 1) s += __shfl_xor_sync(0xffffffffu, s, o);
        if (lane == 0) g_encproj[gw] = s;
    } else if (gw < nEnc + nDec) {
        const int r = gw - nEnc;
        const float4* row = (const float4*)(dec + (size_t)r * HH);
        const float4* w   = (const float4*)(Wg + HH);
        float s = 0.f;
        #pragma unroll
        for (int i = 0; i < HH / 128; ++i) {
            float4 a = row[lane + i * 32];
            float4 b = w[lane + i * 32];
            s += a.x * b.x + a.y * b.y + a.z * b.z + a.w * b.w;
        }
        #pragma unroll
        for (int o = 16; o > 0; o >>= 1) s += __shfl_xor_sync(0xffffffffu, s, o);
        if (lane == 0) g_decproj[r] = s + bg[0];
    }
}

__device__ __forceinline__ float4 xform(float4 x, float c, float pinvS, bool fastp) {
    float4 r;
    if (fastp) {
        r.x = x.x + c; r.y = x.y + c; r.z = x.z + c; r.w = x.w + c;
    } else {
        r.x = __logf(fmaf(pinvS, __expf(x.x), 1e-12f));
        r.y = __logf(fmaf(pinvS, __expf(x.y), 1e-12f));
        r.z = __logf(fmaf(pinvS, __expf(x.z), 1e-12f));
        r.w = __logf(fmaf(pinvS, __expf(x.w), 1e-12f));
    }
    return r;
}

// ---------------------------------------------------------------------------
// Kernel 2: persistent 1 CTA/SM. Segment-granular TMA ring: the row buffer is
// 4 segments, each re-kicked for row r+2G right after its consumption inside
// the merged store/refill loop — load stream flows continuously, interleaved
// with the store stream.
// ---------------------------------------------------------------------------
__global__ __launch_bounds__(1024, 1)
void pgen_fused_kernel(const float* __restrict__ attn,
                       const float* __restrict__ logits,
                       const int*   __restrict__ sids,
                       float*       __restrict__ out)
{
    extern __shared__ __align__(128) char smem[];
    float4* rowbuf = (float4*)(smem + OFF_ROW);
    int*    hkey   = (int*)  (smem + OFF_HKEY);
    float*  hval   = (float*)(smem + OFF_HVAL);
    float*  red    = (float*)(smem + OFF_RED);
    const uint32_t mbar0  = smem_u32(smem + OFF_MBAR);
    const uint32_t rowdst = smem_u32(smem + OFF_ROW);

    const int t    = threadIdx.x;
    const int warp = t >> 5;
    const int lane = t & 31;
    const bool tail = (t + 7 * 1024) < N4;

    hkey[t] = -1;          hval[t] = 0.f;
    hkey[t + 1024] = -1;   hval[t + 1024] = 0.f;
    if (t == 0) {
        #pragma unroll
        for (int j = 0; j < 4; ++j) mbar_init(mbar0 + j * 8, 1);
    }
    __syncthreads();

    int row = blockIdx.x;
    if (row >= NROW) return;

    // ---- prologue: row0 direct load; kick all 4 segment TMAs for row+G ----
    float4 v[8];
    {
        const float4* lrow = (const float4*)(logits + (size_t)row * VV);
        #pragma unroll
        for (int i = 0; i < 7; ++i) v[i] = lrow[t + i * 1024];
        if (tail) v[7] = lrow[t + 7 * 1024];
    }
    if (t == 0 && row + PGRID < NROW) {
        const float* src = logits + (size_t)(row + PGRID) * VV;
        #pragma unroll
        for (int j = 0; j < 4; ++j) {
            const uint32_t bytes = (j < 3) ? SEGB : SEG3B;
            mbar_expect_tx(mbar0 + j * 8, bytes);
            tma_1d_g2s(rowdst + j * SEGB, src + j * (SEGF4 * 4), bytes, mbar0 + j * 8);
        }
    }

    float pg = 0.f;
    {   // scatter row0
        const int b0 = row / TT;
        if (t < TS) {
            const float a  = attn[(size_t)row * TS + t];
            const int   id = sids[b0 * TS + t];
            pg = a * g_encproj[b0 * TS + t];
            int slot = (int)(((unsigned)id * 2654435761u) >> 17) & HMASK;
            for (;;) {
                int prev = atomicCAS(&hkey[slot], -1, id);
                if (prev == -1 || prev == id) { atomicAdd(&hval[slot], a); break; }
                slot = (slot + 1) & HMASK;
            }
        }
    }
    float dp = g_decproj[row];

    // pass A row0
    float se = 0.f, xmn = 1e30f;
    #pragma unroll
    for (int i = 0; i < 7; ++i) {
        se += __expf(v[i].x) + __expf(v[i].y) + __expf(v[i].z) + __expf(v[i].w);
        xmn = fminf(xmn, fminf(fminf(v[i].x, v[i].y), fminf(v[i].z, v[i].w)));
    }
    if (tail) {
        se += __expf(v[7].x) + __expf(v[7].y) + __expf(v[7].z) + __expf(v[7].w);
        xmn = fminf(xmn, fminf(fminf(v[7].x, v[7].y), fminf(v[7].z, v[7].w)));
    }

    // prefetch scatter inputs + decproj for row+G
    float a_in = 0.f, ep_in = 0.f, dp_nxt = 0.f;
    int   id_in = 0;
    if (row + PGRID < NROW) {
        const int bn = (row + PGRID) / TT;
        if (t < TS) {
            a_in  = attn[(size_t)(row + PGRID) * TS + t];
            id_in = sids[bn * TS + t];
            ep_in = g_encproj[bn * TS + t];
        }
        dp_nxt = g_decproj[row + PGRID];
    }

    uint32_t phase = 0;

    while (true) {
        // ---- reduction of (pg, se, xmn) ----
        float rpg = pg, rse = se, rmn = xmn;
        #pragma unroll
        for (int o = 16; o > 0; o >>= 1) {
            rpg += __shfl_xor_sync(0xffffffffu, rpg, o);
            rse += __shfl_xor_sync(0xffffffffu, rse, o);
            rmn  = fminf(rmn, __shfl_xor_sync(0xffffffffu, rmn, o));
        }
        if (lane == 0) { red[warp] = rpg; red[32 + warp] = rse; red[64 + warp] = rmn; }
        __syncthreads();
        if (warp == 0) {
            float a2 = red[lane];
            float s2 = red[32 + lane];
            float m2 = red[64 + lane];
            #pragma unroll
            for (int o = 16; o > 0; o >>= 1) {
                a2 += __shfl_xor_sync(0xffffffffu, a2, o);
                s2 += __shfl_xor_sync(0xffffffffu, s2, o);
                m2  = fminf(m2, __shfl_xor_sync(0xffffffffu, m2, o));
            }
            if (lane == 0) { red[0] = a2; red[32] = s2; red[64] = m2; }
        }
        __syncthreads();

        const float z     = red[0] + dp;
        const float p     = 1.f / (1.f + __expf(-z));
        const float q     = 1.f - p;
        const float pinvS = p / red[32];
        const float c     = __logf(pinvS);
        const bool  fastp = (pinvS * __expf(red[64])) >= 1e-9f;

        // prefetch fixup gathers (hash complete; land under merged loop)
        const float* lsc = logits + (size_t)row * VV;
        const int vid0 = hkey[t];
        const int vid1 = hkey[t + 1024];
        float xf0 = 0.f, xf1 = 0.f, m0 = 0.f, m1 = 0.f;
        if (vid0 >= 0) { xf0 = lsc[vid0]; m0 = hval[t]; }
        if (vid1 >= 0) { xf1 = lsc[vid1]; m1 = hval[t + 1024]; }

        const int  next      = row + PGRID;
        const bool has_next  = next < NROW;
        const bool has_next2 = next + PGRID < NROW;
        const float* src2 = logits + (size_t)(next + PGRID) * VV;

        // ---- merged loop over 4 segments ----
        float4* orow = (float4*)(out + (size_t)row * VV);
        se = 0.f; xmn = 1e30f;
        if (has_next) {
            #pragma unroll
            for (int j = 0; j < 4; ++j) {
                mbar_wait(mbar0 + j * 8, phase);
                const int i0 = 2 * j, i1 = 2 * j + 1;
                // chunk i0 (always full)
                orow[t + i0 * 1024] = xform(v[i0], c, pinvS, fastp);
                v[i0] = rowbuf[t + i0 * 1024];
                se += __expf(v[i0].x) + __expf(v[i0].y) + __expf(v[i0].z) + __expf(v[i0].w);
                xmn = fminf(xmn, fminf(fminf(v[i0].x, v[i0].y), fminf(v[i0].z, v[i0].w)));
                // chunk i1 (chunk 7 partial)
                if (i1 < 7 || tail) {
                    orow[t + i1 * 1024] = xform(v[i1], c, pinvS, fastp);
                    v[i1] = rowbuf[t + i1 * 1024];
                    se += __expf(v[i1].x) + __expf(v[i1].y) + __expf(v[i1].z) + __expf(v[i1].w);
                    xmn = fminf(xmn, fminf(fminf(v[i1].x, v[i1].y), fminf(v[i1].z, v[i1].w)));
                }
                __syncthreads();   // segment j fully consumed
                if (t == 0 && has_next2) {
                    const uint32_t bytes = (j < 3) ? SEGB : SEG3B;
                    mbar_expect_tx(mbar0 + j * 8, bytes);
                    tma_1d_g2s(rowdst + j * SEGB, src2 + j * (SEGF4 * 4),
                               bytes, mbar0 + j * 8);
                }
            }
            phase ^= 1;
        } else {
            #pragma unroll
            for (int i = 0; i < 7; ++i)
                orow[t + i * 1024] = xform(v[i], c, pinvS, fastp);
            if (tail)
                orow[t + 7 * 1024] = xform(v[7], c, pinvS, fastp);
            __syncthreads();   // order stores before fixup overwrites
        }

        // fixup (gathers in registers) + hash clear
        float* osc = out + (size_t)row * VV;
        if (vid0 >= 0) {
            osc[vid0] = __logf(fmaf(pinvS, __expf(xf0), fmaf(q, m0, 1e-12f)));
            hkey[t] = -1;  hval[t] = 0.f;
        }
        if (vid1 >= 0) {
            osc[vid1] = __logf(fmaf(pinvS, __expf(xf1), fmaf(q, m1, 1e-12f)));
            hkey[t + 1024] = -1;  hval[t + 1024] = 0.f;
        }

        if (!has_next) break;

        __syncthreads();   // hash clean before next scatter

        // scatter row r+G (inputs prefetched)
        pg = 0.f;
        if (t < TS) {
            pg = a_in * ep_in;
            int slot = (int)(((unsigned)id_in * 2654435761u) >> 17) & HMASK;
            for (;;) {
                int prev = atomicCAS(&hkey[slot], -1, id_in);
                if (prev == -1 || prev == id_in) { atomicAdd(&hval[slot], a_in); break; }
                slot = (slot + 1) & HMASK;
            }
        }
        dp = dp_nxt;

        // prefetch scatter inputs for row r+2G
        if (has_next2) {
            const int bn = (next + PGRID) / TT;
            if (t < TS) {
                a_in  = attn[(size_t)(next + PGRID) * TS + t];
                id_in = sids[bn * TS + t];
                ep_in = g_encproj[bn * TS + t];
            }
            dp_nxt = g_decproj[next + PGRID];
        }

        row = next;
    }
}

extern "C" void kernel_launch(void* const* d_in, const int* in_sizes, int n_in,
                              void* d_out, int out_size)
{
    const float* dec    = (const float*)d_in[0];
    const float* attn   = (const float*)d_in[1];
    const float* enc    = (const float*)d_in[2];
    const float* logits = (const float*)d_in[3];
    const float* Wg     = (const float*)d_in[4];
    const float* bg     = (const float*)d_in[5];
    const int*   sids   = (const int*)  d_in[6];
    float*       out    = (float*)d_out;

    cudaFuncSetAttribute(pgen_fused_kernel,
                         cudaFuncAttributeMaxDynamicSharedMemorySize, SMEM_TOT);

    proj_kernel<<<(BB * TS + BB * TT) / 8, 256>>>(dec, enc, Wg, bg);
    pgen_fused_kernel<<<PGRID, 1024, SMEM_TOT>>>(attn, logits, sids, out);
}

// round 9
// speedup vs baseline: 1.0370x; 1.0370x over previous
#include <cuda_runtime.h>
#include <stdint.h>
#include <math.h>

#define BB  4
#define TT  256
#define TS  512
#define HH  1024
#define VV  32100
#define NROW (BB*TT)
#define N4  (VV/4)          // 8025 float4 per row
#define ROWBYTES (VV*4)     // 128400 B

#define HSLOTS 2048
#define HMASK  (HSLOTS-1)
#define PGRID  148

// 8 segments, one per register chunk: segs 0-6 = 1024 float4 (16384 B), seg 7 = 857 float4 (13712 B)
#define SEGB    16384
#define SEG7B   (ROWBYTES - 7*SEGB)   // 13712

#define OFF_ROW   0
#define OFF_HKEY  128512
#define OFF_HVAL  (OFF_HKEY + HSLOTS*4)
#define OFF_RED   (OFF_HVAL + HSLOTS*4)
#define OFF_MBAR  (OFF_RED + 96*4)
#define SMEM_TOT  (OFF_MBAR + 8*8 + 16)

__device__ float g_encproj[BB * TS];
__device__ float g_decproj[BB * TT];

__device__ __forceinline__ uint32_t smem_u32(const void* p) {
    uint32_t a;
    asm("{ .reg .u64 t; cvta.to.shared.u64 t, %1; cvt.u32.u64 %0, t; }"
        : "=r"(a) : "l"(p));
    return a;
}
__device__ __forceinline__ void mbar_init(uint32_t mbar, uint32_t cnt) {
    asm volatile("mbarrier.init.shared.b64 [%0], %1;" :: "r"(mbar), "r"(cnt) : "memory");
}
__device__ __forceinline__ void mbar_expect_tx(uint32_t mbar, uint32_t bytes) {
    asm volatile("mbarrier.arrive.expect_tx.shared.b64 _, [%0], %1;"
                 :: "r"(mbar), "r"(bytes) : "memory");
}
__device__ __forceinline__ void mbar_wait(uint32_t mbar, uint32_t phase) {
    asm volatile(
        "{\n\t.reg .pred P;\n\t"
        "W_%=:\n\t"
        "mbarrier.try_wait.parity.acquire.cta.shared::cta.b64 P, [%0], %1, 0x989680;\n\t"
        "@P bra D_%=;\n\t"
        "bra W_%=;\n\t"
        "D_%=:\n\t}"
        :: "r"(mbar), "r"(phase) : "memory");
}
__device__ __forceinline__ void tma_1d_g2s(uint32_t dst, const void* src,
                                           uint32_t bytes, uint32_t mbar) {
    asm volatile(
        "cp.async.bulk.shared::cta.global.mbarrier::complete_tx::bytes [%0], [%1], %2, [%3];"
        :: "r"(dst), "l"(src), "r"(bytes), "r"(mbar) : "memory");
}

// ---------------------------------------------------------------------------
// Kernel 1: one warp per row dot(row, W); replaces the einsum via
//   context . W_top == sum_s attn[s] * (enc[s] . W_top)
// ---------------------------------------------------------------------------
__global__ void proj_kernel(const float* __restrict__ dec,
                            const float* __restrict__ enc,
                            const float* __restrict__ Wg,
                            const float* __restrict__ bg)
{
    const int gw   = (blockIdx.x * blockDim.x + threadIdx.x) >> 5;
    const int lane = threadIdx.x & 31;
    const int nEnc = BB * TS;
    const int nDec = BB * TT;

    if (gw < nEnc) {
        const float4* row = (const float4*)(enc + (size_t)gw * HH);
        const float4* w   = (const float4*)(Wg);
        float s = 0.f;
        #pragma unroll
        for (int i = 0; i < HH / 128; ++i) {
            float4 a = row[lane + i * 32];
            float4 b = w[lane + i * 32];
            s += a.x * b.x + a.y * b.y + a.z * b.z + a.w * b.w;
        }
        #pragma unroll
        for (int o = 16; o > 0; o >>= 1) s += __shfl_xor_sync(0xffffffffu, s, o);
        if (lane == 0) g_encproj[gw] = s;
    } else if (gw < nEnc + nDec) {
        const int r = gw - nEnc;
        const float4* row = (const float4*)(dec + (size_t)r * HH);
        const float4* w   = (const float4*)(Wg + HH);
        float s = 0.f;
        #pragma unroll
        for (int i = 0; i < HH / 128; ++i) {
            float4 a = row[lane + i * 32];
            float4 b = w[lane + i * 32];
            s += a.x * b.x + a.y * b.y + a.z * b.z + a.w * b.w;
        }
        #pragma unroll
        for (int o = 16; o > 0; o >>= 1) s += __shfl_xor_sync(0xffffffffu, s, o);
        if (lane == 0) g_decproj[r] = s + bg[0];
    }
}

__device__ __forceinline__ float4 xform(float4 x, float c, float pinvS, bool fastp) {
    float4 r;
    if (fastp) {
        r.x = x.x + c; r.y = x.y + c; r.z = x.z + c; r.w = x.w + c;
    } else {
        r.x = __logf(fmaf(pinvS, __expf(x.x), 1e-12f));
        r.y = __logf(fmaf(pinvS, __expf(x.y), 1e-12f));
        r.z = __logf(fmaf(pinvS, __expf(x.z), 1e-12f));
        r.w = __logf(fmaf(pinvS, __expf(x.w), 1e-12f));
    }
    return r;
}

// ---------------------------------------------------------------------------
// Kernel 2: persistent 1 CTA/SM, round-7 structure with per-chunk mbarrier
// waits. All 8 segment TMAs for the next row are kicked at ONE point (after
// the single consume-sync); the merged loop stores chunk i, THEN waits only
// segment i, then refills + exp-sums — stores stream during waits, first
// chunks are consumable ~4x earlier than a whole-row wait.
// ---------------------------------------------------------------------------
__global__ __launch_bounds__(1024, 1)
void pgen_fused_kernel(const float* __restrict__ attn,
                       const float* __restrict__ logits,
                       const int*   __restrict__ sids,
                       float*       __restrict__ out)
{
    extern __shared__ __align__(128) char smem[];
    float4* rowbuf = (float4*)(smem + OFF_ROW);
    int*    hkey   = (int*)  (smem + OFF_HKEY);
    float*  hval   = (float*)(smem + OFF_HVAL);
    float*  red    = (float*)(smem + OFF_RED);
    const uint32_t mbar0  = smem_u32(smem + OFF_MBAR);
    const uint32_t rowdst = smem_u32(smem + OFF_ROW);

    const int t    = threadIdx.x;
    const int warp = t >> 5;
    const int lane = t & 31;
    const bool tail = (t + 7 * 1024) < N4;

    hkey[t] = -1;          hval[t] = 0.f;
    hkey[t + 1024] = -1;   hval[t + 1024] = 0.f;
    if (t == 0) {
        #pragma unroll
        for (int j = 0; j < 8; ++j) mbar_init(mbar0 + j * 8, 1);
    }
    __syncthreads();

    int row = blockIdx.x;
    if (row >= NROW) return;

    // ---- prologue: row0 direct load; kick all 8 segment TMAs for row+G ----
    float4 v[8];
    {
        const float4* lrow = (const float4*)(logits + (size_t)row * VV);
        #pragma unroll
        for (int i = 0; i < 7; ++i) v[i] = lrow[t + i * 1024];
        if (tail) v[7] = lrow[t + 7 * 1024];
    }
    if (t == 0 && row + PGRID < NROW) {
        const float* src = logits + (size_t)(row + PGRID) * VV;
        #pragma unroll
        for (int j = 0; j < 8; ++j) {
            const uint32_t bytes = (j < 7) ? SEGB : SEG7B;
            mbar_expect_tx(mbar0 + j * 8, bytes);
            tma_1d_g2s(rowdst + j * SEGB, src + j * 4096, bytes, mbar0 + j * 8);
        }
    }

    float pg = 0.f;
    {   // scatter row0
        const int b0 = row / TT;
        if (t < TS) {
            const float a  = attn[(size_t)row * TS + t];
            const int   id = sids[b0 * TS + t];
            pg = a * g_encproj[b0 * TS + t];
            int slot = (int)(((unsigned)id * 2654435761u) >> 17) & HMASK;
            for (;;) {
                int prev = atomicCAS(&hkey[slot], -1, id);
                if (prev == -1 || prev == id) { atomicAdd(&hval[slot], a); break; }
                slot = (slot + 1) & HMASK;
            }
        }
    }
    float dp = g_decproj[row];

    // pass A row0
    float se = 0.f, xmn = 1e30f;
    #pragma unroll
    for (int i = 0; i < 7; ++i) {
        se += __expf(v[i].x) + __expf(v[i].y) + __expf(v[i].z) + __expf(v[i].w);
        xmn = fminf(xmn, fminf(fminf(v[i].x, v[i].y), fminf(v[i].z, v[i].w)));
    }
    if (tail) {
        se += __expf(v[7].x) + __expf(v[7].y) + __expf(v[7].z) + __expf(v[7].w);
        xmn = fminf(xmn, fminf(fminf(v[7].x, v[7].y), fminf(v[7].z, v[7].w)));
    }

    // prefetch scatter inputs + decproj for row+G
    float a_in = 0.f, ep_in = 0.f, dp_nxt = 0.f;
    int   id_in = 0;
    if (row + PGRID < NROW) {
        const int bn = (row + PGRID) / TT;
        if (t < TS) {
            a_in  = attn[(size_t)(row + PGRID) * TS + t];
            id_in = sids[bn * TS + t];
            ep_in = g_encproj[bn * TS + t];
        }
        dp_nxt = g_decproj[row + PGRID];
    }

    uint32_t phase = 0;

    while (true) {
        // ---- reduction of (pg, se, xmn) ----
        float rpg = pg, rse = se, rmn = xmn;
        #pragma unroll
        for (int o = 16; o > 0; o >>= 1) {
            rpg += __shfl_xor_sync(0xffffffffu, rpg, o);
            rse += __shfl_xor_sync(0xffffffffu, rse, o);
            rmn  = fminf(rmn, __shfl_xor_sync(0xffffffffu, rmn, o));
        }
        if (lane == 0) { red[warp] = rpg; red[32 + warp] = rse; red[64 + warp] = rmn; }
        __syncthreads();
        if (warp == 0) {
            float a2 = red[lane];
            float s2 = red[32 + lane];
            float m2 = red[64 + lane];
            #pragma unroll
            for (int o = 16; o > 0; o >>= 1) {
                a2 += __shfl_xor_sync(0xffffffffu, a2, o);
                s2 += __shfl_xor_sync(0xffffffffu, s2, o);
                m2  = fminf(m2, __shfl_xor_sync(0xffffffffu, m2, o));
            }
            if (lane == 0) { red[0] = a2; red[32] = s2; red[64] = m2; }
        }
        __syncthreads();

        const float z     = red[0] + dp;
        const float p     = 1.f / (1.f + __expf(-z));
        const float q     = 1.f - p;
        const float pinvS = p / red[32];
        const float c     = __logf(pinvS);
        const bool  fastp = (pinvS * __expf(red[64])) >= 1e-9f;

        // prefetch fixup gathers (hash complete; land under merged loop)
        const float* lsc = logits + (size_t)row * VV;
        const int vid0 = hkey[t];
        const int vid1 = hkey[t + 1024];
        float xf0 = 0.f, xf1 = 0.f, m0 = 0.f, m1 = 0.f;
        if (vid0 >= 0) { xf0 = lsc[vid0]; m0 = hval[t]; }
        if (vid1 >= 0) { xf1 = lsc[vid1]; m1 = hval[t + 1024]; }

        const int  next      = row + PGRID;
        const bool has_next  = next < NROW;
        const bool has_next2 = next + PGRID < NROW;

        // ---- merged loop: store chunk i -> wait seg i -> refill + exp-sum ----
        float4* orow = (float4*)(out + (size_t)row * VV);
        se = 0.f; xmn = 1e30f;
        if (has_next) {
            #pragma unroll
            for (int i = 0; i < 8; ++i) {
                const bool live = (i < 7) || tail;
                if (live) orow[t + i * 1024] = xform(v[i], c, pinvS, fastp);
                mbar_wait(mbar0 + i * 8, phase);
                if (live) {
                    v[i] = rowbuf[t + i * 1024];
                    se += __expf(v[i].x) + __expf(v[i].y) + __expf(v[i].z) + __expf(v[i].w);
                    xmn = fminf(xmn, fminf(fminf(v[i].x, v[i].y), fminf(v[i].z, v[i].w)));
                }
            }
            phase ^= 1;
        } else {
            #pragma unroll
            for (int i = 0; i < 7; ++i)
                orow[t + i * 1024] = xform(v[i], c, pinvS, fastp);
            if (tail)
                orow[t + 7 * 1024] = xform(v[7], c, pinvS, fastp);
        }

        // single sync: stores ordered before fixup, rowbuf fully consumed
        __syncthreads();

        // single kick point: all 8 segment TMAs for row r+2G
        if (t == 0 && has_next && has_next2) {
            const float* src2 = logits + (size_t)(next + PGRID) * VV;
            #pragma unroll
            for (int j = 0; j < 8; ++j) {
                const uint32_t bytes = (j < 7) ? SEGB : SEG7B;
                mbar_expect_tx(mbar0 + j * 8, bytes);
                tma_1d_g2s(rowdst + j * SEGB, src2 + j * 4096, bytes, mbar0 + j * 8);
            }
        }

        // fixup (gathers in registers) + hash clear
        float* osc = out + (size_t)row * VV;
        if (vid0 >= 0) {
            osc[vid0] = __logf(fmaf(pinvS, __expf(xf0), fmaf(q, m0, 1e-12f)));
            hkey[t] = -1;  hval[t] = 0.f;
        }
        if (vid1 >= 0) {
            osc[vid1] = __logf(fmaf(pinvS, __expf(xf1), fmaf(q, m1, 1e-12f)));
            hkey[t + 1024] = -1;  hval[t + 1024] = 0.f;
        }

        if (!has_next) break;

        __syncthreads();   // hash clean before next scatter

        // scatter row r+G (inputs prefetched)
        pg = 0.f;
        if (t < TS) {
            pg = a_in * ep_in;
            int slot = (int)(((unsigned)id_in * 2654435761u) >> 17) & HMASK;
            for (;;) {
                int prev = atomicCAS(&hkey[slot], -1, id_in);
                if (prev == -1 || prev == id_in) { atomicAdd(&hval[slot], a_in); break; }
                slot = (slot + 1) & HMASK;
            }
        }
        dp = dp_nxt;

        // prefetch scatter inputs for row r+2G
        if (has_next2) {
            const int bn = (next + PGRID) / TT;
            if (t < TS) {
                a_in  = attn[(size_t)(next + PGRID) * TS + t];
                id_in = sids[bn * TS + t];
                ep_in = g_encproj[bn * TS + t];
            }
            dp_nxt = g_decproj[next + PGRID];
        }

        row = next;
    }
}

extern "C" void kernel_launch(void* const* d_in, const int* in_sizes, int n_in,
                              void* d_out, int out_size)
{
    const float* dec    = (const float*)d_in[0];
    const float* attn   = (const float*)d_in[1];
    const float* enc    = (const float*)d_in[2];
    const float* logits = (const float*)d_in[3];
    const float* Wg     = (const float*)d_in[4];
    const float* bg     = (const float*)d_in[5];
    const int*   sids   = (const int*)  d_in[6];
    float*       out    = (float*)d_out;

    cudaFuncSetAttribute(pgen_fused_kernel,
                         cudaFuncAttributeMaxDynamicSharedMemorySize, SMEM_TOT);

    proj_kernel<<<(BB * TS + BB * TT) / 8, 256>>>(dec, enc, Wg, bg);
    pgen_fused_kernel<<<PGRID, 1024, SMEM_TOT>>>(attn, logits, sids, out);
}